// round 8
// baseline (speedup 1.0000x reference)
#include <cuda_runtime.h>
#include <cuda_bf16.h>
#include <cstdint>

#define B_   32
#define C_   384
#define HW_  4096
#define M_   64
#define R_   16

typedef unsigned long long ull;

// ---------------- f32x2 helpers ----------------
__device__ __forceinline__ ull pk2(float lo, float hi) {
    ull r; asm("mov.b64 %0, {%1, %2};" : "=l"(r) : "f"(lo), "f"(hi)); return r;
}
__device__ __forceinline__ float2 unpk2(ull v) {
    float2 u; asm("mov.b64 {%0, %1}, %2;" : "=f"(u.x), "=f"(u.y) : "l"(v)); return u;
}
__device__ __forceinline__ void fma2(ull &d, ull a, ull b) {
    asm("fma.rn.f32x2 %0, %1, %2, %0;" : "+l"(d) : "l"(a), "l"(b));
}

// ---------------- kernel 1: V = Vw x + Vb ; L = U V ; S = softmax_M(L) ----
// 2 pixels per thread in the V phase (weight LDS amortized 2x).
// Softmax phase: unroll 1 over pixels to bound register pressure.
__global__ __launch_bounds__(128) void k_proj_softmax(
    const float* __restrict__ x,  const float* __restrict__ Vw,
    const float* __restrict__ Vb, const float* __restrict__ U,
    float* __restrict__ S)
{
    __shared__ __align__(16) ull sVw2[C_ * 8];
    __shared__ __align__(16) ull sUT2[R_ * 32];
    __shared__ float sVb[R_];

    const int tid = threadIdx.x;
    for (int i = tid; i < C_ * 8; i += 128) {
        int c = i >> 3, r2 = i & 7;
        sVw2[i] = pk2(Vw[(2 * r2) * C_ + c], Vw[(2 * r2 + 1) * C_ + c]);
    }
    for (int i = tid; i < R_ * 32; i += 128) {
        int r = i >> 5, m2 = i & 31;
        sUT2[i] = pk2(U[(2 * m2) * R_ + r], U[(2 * m2 + 1) * R_ + r]);
    }
    if (tid < R_) sVb[tid] = Vb[tid];
    __syncthreads();

    const int b = blockIdx.y;
    const int n0 = (blockIdx.x << 8) + tid;      // 256 pixels per block
    const float* xp = x + ((size_t)b * C_) * HW_ + n0;

    ull V2[2][8];
#pragma unroll
    for (int p = 0; p < 2; p++)
#pragma unroll
        for (int r2 = 0; r2 < 8; r2++) V2[p][r2] = pk2(sVb[2 * r2], sVb[2 * r2 + 1]);

#pragma unroll 2
    for (int c = 0; c < C_; c++) {
        const ulonglong2* wr = (const ulonglong2*)&sVw2[c * 8];
        ulonglong2 w0 = wr[0], w1 = wr[1], w2 = wr[2], w3 = wr[3];
        float xv0 = xp[(size_t)c * HW_];
        float xv1 = xp[(size_t)c * HW_ + 128];
        ull x20 = pk2(xv0, xv0), x21 = pk2(xv1, xv1);
        fma2(V2[0][0], x20, w0.x); fma2(V2[0][1], x20, w0.y);
        fma2(V2[0][2], x20, w1.x); fma2(V2[0][3], x20, w1.y);
        fma2(V2[0][4], x20, w2.x); fma2(V2[0][5], x20, w2.y);
        fma2(V2[0][6], x20, w3.x); fma2(V2[0][7], x20, w3.y);
        fma2(V2[1][0], x21, w0.x); fma2(V2[1][1], x21, w0.y);
        fma2(V2[1][2], x21, w1.x); fma2(V2[1][3], x21, w1.y);
        fma2(V2[1][4], x21, w2.x); fma2(V2[1][5], x21, w2.y);
        fma2(V2[1][6], x21, w3.x); fma2(V2[1][7], x21, w3.y);
    }

#pragma unroll 1
    for (int p = 0; p < 2; p++) {
        float V[R_];
#pragma unroll
        for (int r2 = 0; r2 < 8; r2++) {
            float2 u = unpk2(V2[p][r2]); V[2 * r2] = u.x; V[2 * r2 + 1] = u.y;
        }
        ull L2[32];
#pragma unroll
        for (int m2 = 0; m2 < 32; m2++) L2[m2] = 0ULL;
#pragma unroll
        for (int r = 0; r < R_; r++) {
            ull v2 = pk2(V[r], V[r]);
            const ulonglong2* ur = (const ulonglong2*)&sUT2[r * 32];
#pragma unroll
            for (int m4 = 0; m4 < 32; m4 += 2) {
                ulonglong2 ua = ur[m4 >> 1];
                fma2(L2[m4], v2, ua.x); fma2(L2[m4 + 1], v2, ua.y);
            }
        }
        float L[M_];
#pragma unroll
        for (int m2 = 0; m2 < 32; m2++) {
            float2 u = unpk2(L2[m2]); L[2 * m2] = u.x; L[2 * m2 + 1] = u.y;
        }
        float mx = -1e30f;
#pragma unroll
        for (int m = 0; m < M_; m++) mx = fmaxf(mx, L[m]);
        float sum = 0.0f;
#pragma unroll
        for (int m = 0; m < M_; m++) { L[m] = __expf(L[m] - mx); sum += L[m]; }
        float inv = 1.0f / sum;

        float* sp = S + ((size_t)b * M_) * HW_ + n0 + (p << 7);
#pragma unroll
        for (int m = 0; m < M_; m++) sp[(size_t)m * HW_] = L[m] * inv;
    }
}

// ================= pool kernel: warp-level bf16 mma.sync =================
// (round-5 proven version, unchanged)
// Per block (c-tile 128, batch b): T[c0+0:128, 0:64] = sum_n x[c,n] S[m,n]
// fp32 split into bf16 (hi, lo); 3-term compensated MMA: AhBh + AhBl + AlBh.

#define CTILE  128
#define KC     64
#define NCHUNK (HW_ / KC)   // 64

#define SM_AHI 0
#define SM_ALO 16384
#define SM_BHI 32768
#define SM_BLO 40960
#define SM_TOTAL 49152

__device__ __forceinline__ uint32_t smem_u32(const void* p) {
    uint32_t a;
    asm("{ .reg .u64 t; cvta.to.shared.u64 t, %1; cvt.u32.u64 %0, t; }"
        : "=r"(a) : "l"(p));
    return a;
}
__device__ __forceinline__ uint32_t sw128(uint32_t off) {
    return off ^ ((off >> 3) & 0x70);
}
__device__ __forceinline__ void ldsm4(uint32_t* r, uint32_t addr) {
    asm volatile("ldmatrix.sync.aligned.m8n8.x4.shared.b16 {%0,%1,%2,%3}, [%4];"
        : "=r"(r[0]), "=r"(r[1]), "=r"(r[2]), "=r"(r[3]) : "r"(addr));
}
__device__ __forceinline__ void mma_bf16(float* d, const uint32_t* a,
                                         const uint32_t* b) {
    asm volatile(
        "mma.sync.aligned.m16n8k16.row.col.f32.bf16.bf16.f32 "
        "{%0,%1,%2,%3}, {%4,%5,%6,%7}, {%8,%9}, {%0,%1,%2,%3};"
        : "+f"(d[0]), "+f"(d[1]), "+f"(d[2]), "+f"(d[3])
        : "r"(a[0]), "r"(a[1]), "r"(a[2]), "r"(a[3]), "r"(b[0]), "r"(b[1]));
}

__global__ __launch_bounds__(256, 1) void k_pool_mma(
    const float* __restrict__ x, const float* __restrict__ S,
    float* __restrict__ T)
{
    extern __shared__ char smem[];
    const uint32_t sb = smem_u32(smem);
    const int tid = threadIdx.x;
    const int w   = tid >> 5;
    const int l   = tid & 31;
    const int c0  = blockIdx.x * CTILE;
    const int b   = blockIdx.y;

    const float* xb = x + ((size_t)b * C_ + c0) * HW_;
    const float* Sb = S + (size_t)b * M_ * HW_;

    const int cp = tid & 31;
    const int r0 = tid >> 5;

    const int arow = 16 * w + (l & 15);
    const int acol = (l >> 4) * 16;
    const int nrow = (l & 7) + ((l >> 4) << 3);
    const int bcol = ((l >> 3) & 1) * 16;

    float acc[8][4];
#pragma unroll
    for (int j = 0; j < 8; j++)
#pragma unroll
        for (int q = 0; q < 4; q++) acc[j][q] = 0.0f;

    float2 av[16], bv[8];
#pragma unroll
    for (int i = 0; i < 16; i++)
        av[i] = *(const float2*)(xb + (size_t)(r0 + 8 * i) * HW_ + 2 * cp);
#pragma unroll
    for (int i = 0; i < 8; i++)
        bv[i] = *(const float2*)(Sb + (size_t)(r0 + 8 * i) * HW_ + 2 * cp);

    for (int ch = 0; ch < NCHUNK; ch++) {
#pragma unroll
        for (int i = 0; i < 16; i++) {
            uint32_t sw = sw128((r0 + 8 * i) * 128 + 4 * cp);
            __nv_bfloat162 h = __floats2bfloat162_rn(av[i].x, av[i].y);
            float rx = av[i].x - __bfloat162float(h.x);
            float ry = av[i].y - __bfloat162float(h.y);
            __nv_bfloat162 lo = __floats2bfloat162_rn(rx, ry);
            *(uint32_t*)(smem + SM_AHI + sw) = *(uint32_t*)&h;
            *(uint32_t*)(smem + SM_ALO + sw) = *(uint32_t*)&lo;
        }
#pragma unroll
        for (int i = 0; i < 8; i++) {
            uint32_t sw = sw128((r0 + 8 * i) * 128 + 4 * cp);
            __nv_bfloat162 h = __floats2bfloat162_rn(bv[i].x, bv[i].y);
            float rx = bv[i].x - __bfloat162float(h.x);
            float ry = bv[i].y - __bfloat162float(h.y);
            __nv_bfloat162 lo = __floats2bfloat162_rn(rx, ry);
            *(uint32_t*)(smem + SM_BHI + sw) = *(uint32_t*)&h;
            *(uint32_t*)(smem + SM_BLO + sw) = *(uint32_t*)&lo;
        }
        __syncthreads();

        if (ch + 1 < NCHUNK) {
            const int k1 = (ch + 1) * KC;
#pragma unroll
            for (int i = 0; i < 16; i++)
                av[i] = *(const float2*)(xb + (size_t)(r0 + 8 * i) * HW_ + k1 + 2 * cp);
#pragma unroll
            for (int i = 0; i < 8; i++)
                bv[i] = *(const float2*)(Sb + (size_t)(r0 + 8 * i) * HW_ + k1 + 2 * cp);
        }

#pragma unroll
        for (int s = 0; s < 4; s++) {
            uint32_t ah[4], al[4];
            uint32_t asw = sw128(arow * 128 + 32 * s + acol);
            ldsm4(ah, sb + SM_AHI + asw);
            ldsm4(al, sb + SM_ALO + asw);
#pragma unroll
            for (int jp = 0; jp < 4; jp++) {
                uint32_t bh[4], bl[4];
                uint32_t bsw = sw128((16 * jp + nrow) * 128 + 32 * s + bcol);
                ldsm4(bh, sb + SM_BHI + bsw);
                ldsm4(bl, sb + SM_BLO + bsw);
                mma_bf16(acc[2 * jp],     ah, bh);
                mma_bf16(acc[2 * jp],     ah, bl);
                mma_bf16(acc[2 * jp],     al, bh);
                mma_bf16(acc[2 * jp + 1], ah, bh + 2);
                mma_bf16(acc[2 * jp + 1], ah, bl + 2);
                mma_bf16(acc[2 * jp + 1], al, bh + 2);
            }
        }
        __syncthreads();
    }

    const int g  = l >> 2;
    const int q2 = (l & 3) * 2;
    float* tb = T + ((size_t)b * C_ + c0 + 16 * w) * M_;
#pragma unroll
    for (int j = 0; j < 8; j++) {
        float2 v0 = make_float2(acc[j][0], acc[j][1]);
        float2 v1 = make_float2(acc[j][2], acc[j][3]);
        *(float2*)(tb + (size_t)g * M_ + 8 * j + q2)       = v0;
        *(float2*)(tb + (size_t)(g + 8) * M_ + 8 * j + q2) = v1;
    }
}

// ---------------- launch ----------------
extern "C" void kernel_launch(void* const* d_in, const int* in_sizes, int n_in,
                              void* d_out, int out_size)
{
    const float* x  = (const float*)d_in[0];
    const float* Vw = (const float*)d_in[1];
    const float* Vb = (const float*)d_in[2];
    const float* U  = (const float*)d_in[3];

    float* out = (float*)d_out;
    float* T = out;                           // [B, C, M]
    float* S = out + (size_t)B_ * C_ * M_;    // [B, M, N]

    cudaFuncSetAttribute(k_pool_mma, cudaFuncAttributeMaxDynamicSharedMemorySize,
                         SM_TOTAL);
    k_proj_softmax<<<dim3(HW_ / 256, B_), 128>>>(x, Vw, Vb, U, S);
    k_pool_mma<<<dim3(C_ / CTILE, B_), 256, SM_TOTAL>>>(x, S, T);
}

// round 9
// speedup vs baseline: 1.8757x; 1.8757x over previous
#include <cuda_runtime.h>
#include <cuda_bf16.h>
#include <cstdint>

#define B_   32
#define C_   384
#define HW_  4096
#define M_   64
#define R_   16

typedef unsigned long long ull;

// ---------------- f32x2 helpers ----------------
__device__ __forceinline__ ull pk2(float lo, float hi) {
    ull r; asm("mov.b64 %0, {%1, %2};" : "=l"(r) : "f"(lo), "f"(hi)); return r;
}
__device__ __forceinline__ float2 unpk2(ull v) {
    float2 u; asm("mov.b64 {%0, %1}, %2;" : "=f"(u.x), "=f"(u.y) : "l"(v)); return u;
}
__device__ __forceinline__ void fma2(ull &d, ull a, ull b) {
    asm("fma.rn.f32x2 %0, %1, %2, %0;" : "+l"(d) : "l"(a), "l"(b));
}

// ---------------- kernel 1: V = Vw x + Vb ; L = U V ; S = softmax_M(L) ----
// (round-5 proven 1-pixel version) + fused zeroing of T.
__global__ __launch_bounds__(128) void k_proj_softmax(
    const float* __restrict__ x,  const float* __restrict__ Vw,
    const float* __restrict__ Vb, const float* __restrict__ U,
    float* __restrict__ S, float* __restrict__ T)
{
    __shared__ __align__(16) ull sVw2[C_ * 8];
    __shared__ __align__(16) ull sUT2[R_ * 32];
    __shared__ float sVb[R_];

    const int tid = threadIdx.x;

    // fused zero of T: 131072 threads x 3 float2 = 786432 floats
    {
        int gt = (blockIdx.y * gridDim.x + blockIdx.x) * 128 + tid;
        float2* tz = (float2*)T + (size_t)gt * 3;
        float2 z = make_float2(0.0f, 0.0f);
        tz[0] = z; tz[1] = z; tz[2] = z;
    }

    for (int i = tid; i < C_ * 8; i += 128) {
        int c = i >> 3, r2 = i & 7;
        sVw2[i] = pk2(Vw[(2 * r2) * C_ + c], Vw[(2 * r2 + 1) * C_ + c]);
    }
    for (int i = tid; i < R_ * 32; i += 128) {
        int r = i >> 5, m2 = i & 31;
        sUT2[i] = pk2(U[(2 * m2) * R_ + r], U[(2 * m2 + 1) * R_ + r]);
    }
    if (tid < R_) sVb[tid] = Vb[tid];
    __syncthreads();

    const int b = blockIdx.y;
    const int n = (blockIdx.x << 7) + tid;
    const float* xp = x + ((size_t)b * C_) * HW_ + n;

    ull V2[8];
#pragma unroll
    for (int r2 = 0; r2 < 8; r2++) V2[r2] = pk2(sVb[2 * r2], sVb[2 * r2 + 1]);

#pragma unroll 4
    for (int c = 0; c < C_; c++) {
        float xv = xp[(size_t)c * HW_];
        ull x2 = pk2(xv, xv);
        const ulonglong2* wr = (const ulonglong2*)&sVw2[c * 8];
        ulonglong2 w0 = wr[0], w1 = wr[1], w2 = wr[2], w3 = wr[3];
        fma2(V2[0], x2, w0.x); fma2(V2[1], x2, w0.y);
        fma2(V2[2], x2, w1.x); fma2(V2[3], x2, w1.y);
        fma2(V2[4], x2, w2.x); fma2(V2[5], x2, w2.y);
        fma2(V2[6], x2, w3.x); fma2(V2[7], x2, w3.y);
    }

    float V[R_];
#pragma unroll
    for (int r2 = 0; r2 < 8; r2++) {
        float2 u = unpk2(V2[r2]); V[2 * r2] = u.x; V[2 * r2 + 1] = u.y;
    }

    ull L2[32];
#pragma unroll
    for (int m2 = 0; m2 < 32; m2++) L2[m2] = 0ULL;
#pragma unroll
    for (int r = 0; r < R_; r++) {
        ull v2 = pk2(V[r], V[r]);
        const ulonglong2* ur = (const ulonglong2*)&sUT2[r * 32];
#pragma unroll
        for (int m4 = 0; m4 < 32; m4 += 2) {
            ulonglong2 ua = ur[m4 >> 1];
            fma2(L2[m4], v2, ua.x); fma2(L2[m4 + 1], v2, ua.y);
        }
    }

    float L[M_];
#pragma unroll
    for (int m2 = 0; m2 < 32; m2++) {
        float2 u = unpk2(L2[m2]); L[2 * m2] = u.x; L[2 * m2 + 1] = u.y;
    }
    float mx = -1e30f;
#pragma unroll
    for (int m = 0; m < M_; m++) mx = fmaxf(mx, L[m]);
    float sum = 0.0f;
#pragma unroll
    for (int m = 0; m < M_; m++) { L[m] = __expf(L[m] - mx); sum += L[m]; }
    float inv = 1.0f / sum;

    float* sp = S + ((size_t)b * M_) * HW_ + n;
#pragma unroll
    for (int m = 0; m < M_; m++) sp[(size_t)m * HW_] = L[m] * inv;
}

// ================= pool kernel: warp-level bf16 mma.sync =================
// Round-5 body, K-split 3 (grid.z): chunks 22/21/21, atomicAdd into zeroed T.

#define CTILE  128
#define KC     64
#define NCHUNK (HW_ / KC)   // 64

#define SM_AHI 0
#define SM_ALO 16384
#define SM_BHI 32768
#define SM_BLO 40960
#define SM_TOTAL 49152

__device__ __forceinline__ uint32_t smem_u32(const void* p) {
    uint32_t a;
    asm("{ .reg .u64 t; cvta.to.shared.u64 t, %1; cvt.u32.u64 %0, t; }"
        : "=r"(a) : "l"(p));
    return a;
}
__device__ __forceinline__ uint32_t sw128(uint32_t off) {
    return off ^ ((off >> 3) & 0x70);
}
__device__ __forceinline__ void ldsm4(uint32_t* r, uint32_t addr) {
    asm volatile("ldmatrix.sync.aligned.m8n8.x4.shared.b16 {%0,%1,%2,%3}, [%4];"
        : "=r"(r[0]), "=r"(r[1]), "=r"(r[2]), "=r"(r[3]) : "r"(addr));
}
__device__ __forceinline__ void mma_bf16(float* d, const uint32_t* a,
                                         const uint32_t* b) {
    asm volatile(
        "mma.sync.aligned.m16n8k16.row.col.f32.bf16.bf16.f32 "
        "{%0,%1,%2,%3}, {%4,%5,%6,%7}, {%8,%9}, {%0,%1,%2,%3};"
        : "+f"(d[0]), "+f"(d[1]), "+f"(d[2]), "+f"(d[3])
        : "r"(a[0]), "r"(a[1]), "r"(a[2]), "r"(a[3]), "r"(b[0]), "r"(b[1]));
}

__global__ __launch_bounds__(256, 1) void k_pool_mma(
    const float* __restrict__ x, const float* __restrict__ S,
    float* __restrict__ T)
{
    extern __shared__ char smem[];
    const uint32_t sb = smem_u32(smem);
    const int tid = threadIdx.x;
    const int w   = tid >> 5;
    const int l   = tid & 31;
    const int c0  = blockIdx.x * CTILE;
    const int b   = blockIdx.y;
    const int ks  = blockIdx.z;                   // 0..2

    const int start = (ks == 0) ? 0 : (22 + 21 * (ks - 1));
    const int cnt   = (ks == 0) ? 22 : 21;

    const float* xb = x + ((size_t)b * C_ + c0) * HW_;
    const float* Sb = S + (size_t)b * M_ * HW_;

    const int cp = tid & 31;
    const int r0 = tid >> 5;

    const int arow = 16 * w + (l & 15);
    const int acol = (l >> 4) * 16;
    const int nrow = (l & 7) + ((l >> 4) << 3);
    const int bcol = ((l >> 3) & 1) * 16;

    float acc[8][4];
#pragma unroll
    for (int j = 0; j < 8; j++)
#pragma unroll
        for (int q = 0; q < 4; q++) acc[j][q] = 0.0f;

    float2 av[16], bv[8];
    {
        const int k0 = start * KC;
#pragma unroll
        for (int i = 0; i < 16; i++)
            av[i] = *(const float2*)(xb + (size_t)(r0 + 8 * i) * HW_ + k0 + 2 * cp);
#pragma unroll
        for (int i = 0; i < 8; i++)
            bv[i] = *(const float2*)(Sb + (size_t)(r0 + 8 * i) * HW_ + k0 + 2 * cp);
    }

    for (int ci = 0; ci < cnt; ci++) {
#pragma unroll
        for (int i = 0; i < 16; i++) {
            uint32_t sw = sw128((r0 + 8 * i) * 128 + 4 * cp);
            __nv_bfloat162 h = __floats2bfloat162_rn(av[i].x, av[i].y);
            float rx = av[i].x - __bfloat162float(h.x);
            float ry = av[i].y - __bfloat162float(h.y);
            __nv_bfloat162 lo = __floats2bfloat162_rn(rx, ry);
            *(uint32_t*)(smem + SM_AHI + sw) = *(uint32_t*)&h;
            *(uint32_t*)(smem + SM_ALO + sw) = *(uint32_t*)&lo;
        }
#pragma unroll
        for (int i = 0; i < 8; i++) {
            uint32_t sw = sw128((r0 + 8 * i) * 128 + 4 * cp);
            __nv_bfloat162 h = __floats2bfloat162_rn(bv[i].x, bv[i].y);
            float rx = bv[i].x - __bfloat162float(h.x);
            float ry = bv[i].y - __bfloat162float(h.y);
            __nv_bfloat162 lo = __floats2bfloat162_rn(rx, ry);
            *(uint32_t*)(smem + SM_BHI + sw) = *(uint32_t*)&h;
            *(uint32_t*)(smem + SM_BLO + sw) = *(uint32_t*)&lo;
        }
        __syncthreads();

        if (ci + 1 < cnt) {
            const int k1 = (start + ci + 1) * KC;
#pragma unroll
            for (int i = 0; i < 16; i++)
                av[i] = *(const float2*)(xb + (size_t)(r0 + 8 * i) * HW_ + k1 + 2 * cp);
#pragma unroll
            for (int i = 0; i < 8; i++)
                bv[i] = *(const float2*)(Sb + (size_t)(r0 + 8 * i) * HW_ + k1 + 2 * cp);
        }

#pragma unroll
        for (int s = 0; s < 4; s++) {
            uint32_t ah[4], al[4];
            uint32_t asw = sw128(arow * 128 + 32 * s + acol);
            ldsm4(ah, sb + SM_AHI + asw);
            ldsm4(al, sb + SM_ALO + asw);
#pragma unroll
            for (int jp = 0; jp < 4; jp++) {
                uint32_t bh[4], bl[4];
                uint32_t bsw = sw128((16 * jp + nrow) * 128 + 32 * s + bcol);
                ldsm4(bh, sb + SM_BHI + bsw);
                ldsm4(bl, sb + SM_BLO + bsw);
                mma_bf16(acc[2 * jp],     ah, bh);
                mma_bf16(acc[2 * jp],     ah, bl);
                mma_bf16(acc[2 * jp],     al, bh);
                mma_bf16(acc[2 * jp + 1], ah, bh + 2);
                mma_bf16(acc[2 * jp + 1], ah, bl + 2);
                mma_bf16(acc[2 * jp + 1], al, bh + 2);
            }
        }
        __syncthreads();
    }

    const int g  = l >> 2;
    const int q2 = (l & 3) * 2;
    float* tb = T + ((size_t)b * C_ + c0 + 16 * w) * M_;
#pragma unroll
    for (int j = 0; j < 8; j++) {
        atomicAdd(tb + (size_t)g * M_ + 8 * j + q2,           acc[j][0]);
        atomicAdd(tb + (size_t)g * M_ + 8 * j + q2 + 1,       acc[j][1]);
        atomicAdd(tb + (size_t)(g + 8) * M_ + 8 * j + q2,     acc[j][2]);
        atomicAdd(tb + (size_t)(g + 8) * M_ + 8 * j + q2 + 1, acc[j][3]);
    }
}

// ---------------- launch ----------------
extern "C" void kernel_launch(void* const* d_in, const int* in_sizes, int n_in,
                              void* d_out, int out_size)
{
    const float* x  = (const float*)d_in[0];
    const float* Vw = (const float*)d_in[1];
    const float* Vb = (const float*)d_in[2];
    const float* U  = (const float*)d_in[3];

    float* out = (float*)d_out;
    float* T = out;                           // [B, C, M]
    float* S = out + (size_t)B_ * C_ * M_;    // [B, M, N]

    cudaFuncSetAttribute(k_pool_mma, cudaFuncAttributeMaxDynamicSharedMemorySize,
                         SM_TOTAL);
    k_proj_softmax<<<dim3(HW_ / 128, B_), 128>>>(x, Vw, Vb, U, S, T);
    k_pool_mma<<<dim3(C_ / CTILE, B_, 3), 256, SM_TOTAL>>>(x, S, T);
}

// round 10
// speedup vs baseline: 2.3377x; 1.2463x over previous
#include <cuda_runtime.h>
#include <cuda_bf16.h>
#include <cstdint>

#define B_   32
#define C_   384
#define HW_  4096
#define M_   64
#define R_   16

typedef unsigned long long ull;

// scratch for V = Vw x + Vb, layout [b][n][16]
__device__ float g_V[(size_t)B_ * HW_ * R_];

// ---------------- f32x2 helpers ----------------
__device__ __forceinline__ ull pk2(float lo, float hi) {
    ull r; asm("mov.b64 %0, {%1, %2};" : "=l"(r) : "f"(lo), "f"(hi)); return r;
}
__device__ __forceinline__ float2 unpk2(ull v) {
    float2 u; asm("mov.b64 {%0, %1}, %2;" : "=f"(u.x), "=f"(u.y) : "l"(v)); return u;
}
__device__ __forceinline__ void fma2(ull &d, ull a, ull b) {
    asm("fma.rn.f32x2 %0, %1, %2, %0;" : "+l"(d) : "l"(a), "l"(b));
}

// ---------------- kernel A: V = Vw x + Vb (low-reg, high-MLP) --------------
// grid (HW/256, B), 256 threads, 1 pixel/thread. Also zeroes T.
__global__ __launch_bounds__(256) void k_v(
    const float* __restrict__ x, const float* __restrict__ Vw,
    const float* __restrict__ Vb, float* __restrict__ T)
{
    __shared__ __align__(16) ull sVw2[C_ * 8];
    __shared__ float sVb[R_];

    const int tid = threadIdx.x;

    // fused zero of T: 512 blocks x 256 thr = 131072 threads x 6 floats
    {
        int gt = (blockIdx.y * gridDim.x + blockIdx.x) * 256 + tid;
        float2* tz = (float2*)T + (size_t)gt * 3;
        float2 z = make_float2(0.0f, 0.0f);
        tz[0] = z; tz[1] = z; tz[2] = z;
    }

    for (int i = tid; i < C_ * 8; i += 256) {
        int c = i >> 3, r2 = i & 7;
        sVw2[i] = pk2(Vw[(2 * r2) * C_ + c], Vw[(2 * r2 + 1) * C_ + c]);
    }
    if (tid < R_) sVb[tid] = Vb[tid];
    __syncthreads();

    const int b = blockIdx.y;
    const int n = (blockIdx.x << 8) + tid;
    const float* xp = x + ((size_t)b * C_) * HW_ + n;

    ull V2[8];
#pragma unroll
    for (int r2 = 0; r2 < 8; r2++) V2[r2] = pk2(sVb[2 * r2], sVb[2 * r2 + 1]);

#pragma unroll 8
    for (int c = 0; c < C_; c++) {
        float xv = xp[(size_t)c * HW_];
        ull x2 = pk2(xv, xv);
        const ulonglong2* wr = (const ulonglong2*)&sVw2[c * 8];
        ulonglong2 w0 = wr[0], w1 = wr[1], w2 = wr[2], w3 = wr[3];
        fma2(V2[0], x2, w0.x); fma2(V2[1], x2, w0.y);
        fma2(V2[2], x2, w1.x); fma2(V2[3], x2, w1.y);
        fma2(V2[4], x2, w2.x); fma2(V2[5], x2, w2.y);
        fma2(V2[6], x2, w3.x); fma2(V2[7], x2, w3.y);
    }

    // write V[b][n][0:16] = 64B contiguous per thread
    ull* vp = (ull*)(g_V + ((size_t)b * HW_ + n) * R_);
#pragma unroll
    for (int r2 = 0; r2 < 8; r2 += 2) {
        ulonglong2 v2; v2.x = V2[r2]; v2.y = V2[r2 + 1];
        *(ulonglong2*)(vp + r2) = v2;
    }
}

// ---------------- kernel B: L = U V ; S = softmax_M(L) ----------------
// grid (HW/128, B), 128 threads, 1 pixel/thread.
__global__ __launch_bounds__(128) void k_softmax(
    const float* __restrict__ U, float* __restrict__ S)
{
    __shared__ __align__(16) ull sUT2[R_ * 32];

    const int tid = threadIdx.x;
    for (int i = tid; i < R_ * 32; i += 128) {
        int r = i >> 5, m2 = i & 31;
        sUT2[i] = pk2(U[(2 * m2) * R_ + r], U[(2 * m2 + 1) * R_ + r]);
    }
    __syncthreads();

    const int b = blockIdx.y;
    const int n = (blockIdx.x << 7) + tid;

    // read V[b][n][0:16]
    float V[R_];
    {
        const ulonglong2* vp = (const ulonglong2*)(g_V + ((size_t)b * HW_ + n) * R_);
#pragma unroll
        for (int q = 0; q < 4; q++) {
            ulonglong2 v2 = vp[q];
            float2 a = unpk2(v2.x), c = unpk2(v2.y);
            V[4 * q] = a.x; V[4 * q + 1] = a.y;
            V[4 * q + 2] = c.x; V[4 * q + 3] = c.y;
        }
    }

    ull L2[32];
#pragma unroll
    for (int m2 = 0; m2 < 32; m2++) L2[m2] = 0ULL;
#pragma unroll
    for (int r = 0; r < R_; r++) {
        ull v2 = pk2(V[r], V[r]);
        const ulonglong2* ur = (const ulonglong2*)&sUT2[r * 32];
#pragma unroll
        for (int m4 = 0; m4 < 32; m4 += 2) {
            ulonglong2 ua = ur[m4 >> 1];
            fma2(L2[m4], v2, ua.x); fma2(L2[m4 + 1], v2, ua.y);
        }
    }

    float L[M_];
#pragma unroll
    for (int m2 = 0; m2 < 32; m2++) {
        float2 u = unpk2(L2[m2]); L[2 * m2] = u.x; L[2 * m2 + 1] = u.y;
    }
    float mx = -1e30f;
#pragma unroll
    for (int m = 0; m < M_; m++) mx = fmaxf(mx, L[m]);
    float sum = 0.0f;
#pragma unroll
    for (int m = 0; m < M_; m++) { L[m] = __expf(L[m] - mx); sum += L[m]; }
    float inv = 1.0f / sum;

    float* sp = S + ((size_t)b * M_) * HW_ + n;
#pragma unroll
    for (int m = 0; m < M_; m++) sp[(size_t)m * HW_] = L[m] * inv;
}

// ================= pool kernel: warp-level bf16 mma.sync =================
// (round-9 proven version, unchanged)
// K-split 3 (grid.z): chunks 22/21/21, atomicAdd into zeroed T.

#define CTILE  128
#define KC     64

#define SM_AHI 0
#define SM_ALO 16384
#define SM_BHI 32768
#define SM_BLO 40960
#define SM_TOTAL 49152

__device__ __forceinline__ uint32_t smem_u32(const void* p) {
    uint32_t a;
    asm("{ .reg .u64 t; cvta.to.shared.u64 t, %1; cvt.u32.u64 %0, t; }"
        : "=r"(a) : "l"(p));
    return a;
}
__device__ __forceinline__ uint32_t sw128(uint32_t off) {
    return off ^ ((off >> 3) & 0x70);
}
__device__ __forceinline__ void ldsm4(uint32_t* r, uint32_t addr) {
    asm volatile("ldmatrix.sync.aligned.m8n8.x4.shared.b16 {%0,%1,%2,%3}, [%4];"
        : "=r"(r[0]), "=r"(r[1]), "=r"(r[2]), "=r"(r[3]) : "r"(addr));
}
__device__ __forceinline__ void mma_bf16(float* d, const uint32_t* a,
                                         const uint32_t* b) {
    asm volatile(
        "mma.sync.aligned.m16n8k16.row.col.f32.bf16.bf16.f32 "
        "{%0,%1,%2,%3}, {%4,%5,%6,%7}, {%8,%9}, {%0,%1,%2,%3};"
        : "+f"(d[0]), "+f"(d[1]), "+f"(d[2]), "+f"(d[3])
        : "r"(a[0]), "r"(a[1]), "r"(a[2]), "r"(a[3]), "r"(b[0]), "r"(b[1]));
}

__global__ __launch_bounds__(256, 1) void k_pool_mma(
    const float* __restrict__ x, const float* __restrict__ S,
    float* __restrict__ T)
{
    extern __shared__ char smem[];
    const uint32_t sb = smem_u32(smem);
    const int tid = threadIdx.x;
    const int w   = tid >> 5;
    const int l   = tid & 31;
    const int c0  = blockIdx.x * CTILE;
    const int b   = blockIdx.y;
    const int ks  = blockIdx.z;                   // 0..2

    const int start = (ks == 0) ? 0 : (22 + 21 * (ks - 1));
    const int cnt   = (ks == 0) ? 22 : 21;

    const float* xb = x + ((size_t)b * C_ + c0) * HW_;
    const float* Sb = S + (size_t)b * M_ * HW_;

    const int cp = tid & 31;
    const int r0 = tid >> 5;

    const int arow = 16 * w + (l & 15);
    const int acol = (l >> 4) * 16;
    const int nrow = (l & 7) + ((l >> 4) << 3);
    const int bcol = ((l >> 3) & 1) * 16;

    float acc[8][4];
#pragma unroll
    for (int j = 0; j < 8; j++)
#pragma unroll
        for (int q = 0; q < 4; q++) acc[j][q] = 0.0f;

    float2 av[16], bv[8];
    {
        const int k0 = start * KC;
#pragma unroll
        for (int i = 0; i < 16; i++)
            av[i] = *(const float2*)(xb + (size_t)(r0 + 8 * i) * HW_ + k0 + 2 * cp);
#pragma unroll
        for (int i = 0; i < 8; i++)
            bv[i] = *(const float2*)(Sb + (size_t)(r0 + 8 * i) * HW_ + k0 + 2 * cp);
    }

    for (int ci = 0; ci < cnt; ci++) {
#pragma unroll
        for (int i = 0; i < 16; i++) {
            uint32_t sw = sw128((r0 + 8 * i) * 128 + 4 * cp);
            __nv_bfloat162 h = __floats2bfloat162_rn(av[i].x, av[i].y);
            float rx = av[i].x - __bfloat162float(h.x);
            float ry = av[i].y - __bfloat162float(h.y);
            __nv_bfloat162 lo = __floats2bfloat162_rn(rx, ry);
            *(uint32_t*)(smem + SM_AHI + sw) = *(uint32_t*)&h;
            *(uint32_t*)(smem + SM_ALO + sw) = *(uint32_t*)&lo;
        }
#pragma unroll
        for (int i = 0; i < 8; i++) {
            uint32_t sw = sw128((r0 + 8 * i) * 128 + 4 * cp);
            __nv_bfloat162 h = __floats2bfloat162_rn(bv[i].x, bv[i].y);
            float rx = bv[i].x - __bfloat162float(h.x);
            float ry = bv[i].y - __bfloat162float(h.y);
            __nv_bfloat162 lo = __floats2bfloat162_rn(rx, ry);
            *(uint32_t*)(smem + SM_BHI + sw) = *(uint32_t*)&h;
            *(uint32_t*)(smem + SM_BLO + sw) = *(uint32_t*)&lo;
        }
        __syncthreads();

        if (ci + 1 < cnt) {
            const int k1 = (start + ci + 1) * KC;
#pragma unroll
            for (int i = 0; i < 16; i++)
                av[i] = *(const float2*)(xb + (size_t)(r0 + 8 * i) * HW_ + k1 + 2 * cp);
#pragma unroll
            for (int i = 0; i < 8; i++)
                bv[i] = *(const float2*)(Sb + (size_t)(r0 + 8 * i) * HW_ + k1 + 2 * cp);
        }

#pragma unroll
        for (int s = 0; s < 4; s++) {
            uint32_t ah[4], al[4];
            uint32_t asw = sw128(arow * 128 + 32 * s + acol);
            ldsm4(ah, sb + SM_AHI + asw);
            ldsm4(al, sb + SM_ALO + asw);
#pragma unroll
            for (int jp = 0; jp < 4; jp++) {
                uint32_t bh[4], bl[4];
                uint32_t bsw = sw128((16 * jp + nrow) * 128 + 32 * s + bcol);
                ldsm4(bh, sb + SM_BHI + bsw);
                ldsm4(bl, sb + SM_BLO + bsw);
                mma_bf16(acc[2 * jp],     ah, bh);
                mma_bf16(acc[2 * jp],     ah, bl);
                mma_bf16(acc[2 * jp],     al, bh);
                mma_bf16(acc[2 * jp + 1], ah, bh + 2);
                mma_bf16(acc[2 * jp + 1], ah, bl + 2);
                mma_bf16(acc[2 * jp + 1], al, bh + 2);
            }
        }
        __syncthreads();
    }

    const int g  = l >> 2;
    const int q2 = (l & 3) * 2;
    float* tb = T + ((size_t)b * C_ + c0 + 16 * w) * M_;
#pragma unroll
    for (int j = 0; j < 8; j++) {
        atomicAdd(tb + (size_t)g * M_ + 8 * j + q2,           acc[j][0]);
        atomicAdd(tb + (size_t)g * M_ + 8 * j + q2 + 1,       acc[j][1]);
        atomicAdd(tb + (size_t)(g + 8) * M_ + 8 * j + q2,     acc[j][2]);
        atomicAdd(tb + (size_t)(g + 8) * M_ + 8 * j + q2 + 1, acc[j][3]);
    }
}

// ---------------- launch ----------------
extern "C" void kernel_launch(void* const* d_in, const int* in_sizes, int n_in,
                              void* d_out, int out_size)
{
    const float* x  = (const float*)d_in[0];
    const float* Vw = (const float*)d_in[1];
    const float* Vb = (const float*)d_in[2];
    const float* U  = (const float*)d_in[3];

    float* out = (float*)d_out;
    float* T = out;                           // [B, C, M]
    float* S = out + (size_t)B_ * C_ * M_;    // [B, M, N]

    cudaFuncSetAttribute(k_pool_mma, cudaFuncAttributeMaxDynamicSharedMemorySize,
                         SM_TOTAL);
    k_v<<<dim3(HW_ / 256, B_), 256>>>(x, Vw, Vb, T);
    k_softmax<<<dim3(HW_ / 128, B_), 128>>>(U, S);
    k_pool_mma<<<dim3(C_ / CTILE, B_, 3), 256, SM_TOTAL>>>(x, S, T);
}

// round 11
// speedup vs baseline: 2.3543x; 1.0071x over previous
#include <cuda_runtime.h>
#include <cuda_bf16.h>
#include <cstdint>

#define B_   32
#define C_   384
#define HW_  4096
#define M_   64
#define R_   16

typedef unsigned long long ull;

// scratch for V = Vw x + Vb, layout [b][n][16]
__device__ float g_V[(size_t)B_ * HW_ * R_];

// ---------------- f32x2 helpers ----------------
__device__ __forceinline__ ull pk2(float lo, float hi) {
    ull r; asm("mov.b64 %0, {%1, %2};" : "=l"(r) : "f"(lo), "f"(hi)); return r;
}
__device__ __forceinline__ float2 unpk2(ull v) {
    float2 u; asm("mov.b64 {%0, %1}, %2;" : "=f"(u.x), "=f"(u.y) : "l"(v)); return u;
}
__device__ __forceinline__ void fma2(ull &d, ull a, ull b) {
    asm("fma.rn.f32x2 %0, %1, %2, %0;" : "+l"(d) : "l"(a), "l"(b));
}

// ---------------- kernel A: V = Vw x + Vb -------------------------------
// 2 pixels/thread (weight LDS amortized 2x), no softmax -> low regs.
// grid (HW/512, B), 256 threads. Also zeroes T.
__global__ __launch_bounds__(256) void k_v(
    const float* __restrict__ x, const float* __restrict__ Vw,
    const float* __restrict__ Vb, float* __restrict__ T)
{
    __shared__ __align__(16) ull sVw2[C_ * 8];
    __shared__ float sVb[R_];

    const int tid = threadIdx.x;

    // fused zero of T: 256 blocks x 256 thr = 65536 threads x 12 floats
    {
        int gt = (blockIdx.y * gridDim.x + blockIdx.x) * 256 + tid;
        float2* tz = (float2*)T + (size_t)gt * 6;
        float2 z = make_float2(0.0f, 0.0f);
        tz[0] = z; tz[1] = z; tz[2] = z; tz[3] = z; tz[4] = z; tz[5] = z;
    }

    for (int i = tid; i < C_ * 8; i += 256) {
        int c = i >> 3, r2 = i & 7;
        sVw2[i] = pk2(Vw[(2 * r2) * C_ + c], Vw[(2 * r2 + 1) * C_ + c]);
    }
    if (tid < R_) sVb[tid] = Vb[tid];
    __syncthreads();

    const int b = blockIdx.y;
    const int n = (blockIdx.x << 9) + tid;      // pixels n and n+256
    const float* xp = x + ((size_t)b * C_) * HW_ + n;

    ull V2[2][8];
#pragma unroll
    for (int p = 0; p < 2; p++)
#pragma unroll
        for (int r2 = 0; r2 < 8; r2++) V2[p][r2] = pk2(sVb[2 * r2], sVb[2 * r2 + 1]);

#pragma unroll 8
    for (int c = 0; c < C_; c++) {
        const ulonglong2* wr = (const ulonglong2*)&sVw2[c * 8];
        ulonglong2 w0 = wr[0], w1 = wr[1], w2 = wr[2], w3 = wr[3];
        float xv0 = xp[(size_t)c * HW_];
        float xv1 = xp[(size_t)c * HW_ + 256];
        ull x20 = pk2(xv0, xv0), x21 = pk2(xv1, xv1);
        fma2(V2[0][0], x20, w0.x); fma2(V2[0][1], x20, w0.y);
        fma2(V2[0][2], x20, w1.x); fma2(V2[0][3], x20, w1.y);
        fma2(V2[0][4], x20, w2.x); fma2(V2[0][5], x20, w2.y);
        fma2(V2[0][6], x20, w3.x); fma2(V2[0][7], x20, w3.y);
        fma2(V2[1][0], x21, w0.x); fma2(V2[1][1], x21, w0.y);
        fma2(V2[1][2], x21, w1.x); fma2(V2[1][3], x21, w1.y);
        fma2(V2[1][4], x21, w2.x); fma2(V2[1][5], x21, w2.y);
        fma2(V2[1][6], x21, w3.x); fma2(V2[1][7], x21, w3.y);
    }

#pragma unroll
    for (int p = 0; p < 2; p++) {
        ull* vp = (ull*)(g_V + ((size_t)b * HW_ + n + (p << 8)) * R_);
#pragma unroll
        for (int r2 = 0; r2 < 8; r2 += 2) {
            ulonglong2 v2; v2.x = V2[p][r2]; v2.y = V2[p][r2 + 1];
            *(ulonglong2*)(vp + r2) = v2;
        }
    }
}

// ---------------- kernel B: L = U V ; S = softmax_M(L) ----------------
// grid (HW/128, B), 128 threads, 1 pixel/thread.
__global__ __launch_bounds__(128) void k_softmax(
    const float* __restrict__ U, float* __restrict__ S)
{
    __shared__ __align__(16) ull sUT2[R_ * 32];

    const int tid = threadIdx.x;
    for (int i = tid; i < R_ * 32; i += 128) {
        int r = i >> 5, m2 = i & 31;
        sUT2[i] = pk2(U[(2 * m2) * R_ + r], U[(2 * m2 + 1) * R_ + r]);
    }
    __syncthreads();

    const int b = blockIdx.y;
    const int n = (blockIdx.x << 7) + tid;

    float V[R_];
    {
        const ulonglong2* vp = (const ulonglong2*)(g_V + ((size_t)b * HW_ + n) * R_);
#pragma unroll
        for (int q = 0; q < 4; q++) {
            ulonglong2 v2 = vp[q];
            float2 a = unpk2(v2.x), c = unpk2(v2.y);
            V[4 * q] = a.x; V[4 * q + 1] = a.y;
            V[4 * q + 2] = c.x; V[4 * q + 3] = c.y;
        }
    }

    ull L2[32];
#pragma unroll
    for (int m2 = 0; m2 < 32; m2++) L2[m2] = 0ULL;
#pragma unroll
    for (int r = 0; r < R_; r++) {
        ull v2 = pk2(V[r], V[r]);
        const ulonglong2* ur = (const ulonglong2*)&sUT2[r * 32];
#pragma unroll
        for (int m4 = 0; m4 < 32; m4 += 2) {
            ulonglong2 ua = ur[m4 >> 1];
            fma2(L2[m4], v2, ua.x); fma2(L2[m4 + 1], v2, ua.y);
        }
    }

    float L[M_];
#pragma unroll
    for (int m2 = 0; m2 < 32; m2++) {
        float2 u = unpk2(L2[m2]); L[2 * m2] = u.x; L[2 * m2 + 1] = u.y;
    }
    float mx = -1e30f;
#pragma unroll
    for (int m = 0; m < M_; m++) mx = fmaxf(mx, L[m]);
    float sum = 0.0f;
#pragma unroll
    for (int m = 0; m < M_; m++) { L[m] = __expf(L[m] - mx); sum += L[m]; }
    float inv = 1.0f / sum;

    float* sp = S + ((size_t)b * M_) * HW_ + n;
#pragma unroll
    for (int m = 0; m < M_; m++) sp[(size_t)m * HW_] = L[m] * inv;
}

// ================= pool kernel: warp-level bf16 mma.sync =================
// (round-9 proven version, unchanged)
// K-split 3 (grid.z): chunks 22/21/21, atomicAdd into zeroed T.

#define CTILE  128
#define KC     64

#define SM_AHI 0
#define SM_ALO 16384
#define SM_BHI 32768
#define SM_BLO 40960
#define SM_TOTAL 49152

__device__ __forceinline__ uint32_t smem_u32(const void* p) {
    uint32_t a;
    asm("{ .reg .u64 t; cvta.to.shared.u64 t, %1; cvt.u32.u64 %0, t; }"
        : "=r"(a) : "l"(p));
    return a;
}
__device__ __forceinline__ uint32_t sw128(uint32_t off) {
    return off ^ ((off >> 3) & 0x70);
}
__device__ __forceinline__ void ldsm4(uint32_t* r, uint32_t addr) {
    asm volatile("ldmatrix.sync.aligned.m8n8.x4.shared.b16 {%0,%1,%2,%3}, [%4];"
        : "=r"(r[0]), "=r"(r[1]), "=r"(r[2]), "=r"(r[3]) : "r"(addr));
}
__device__ __forceinline__ void mma_bf16(float* d, const uint32_t* a,
                                         const uint32_t* b) {
    asm volatile(
        "mma.sync.aligned.m16n8k16.row.col.f32.bf16.bf16.f32 "
        "{%0,%1,%2,%3}, {%4,%5,%6,%7}, {%8,%9}, {%0,%1,%2,%3};"
        : "+f"(d[0]), "+f"(d[1]), "+f"(d[2]), "+f"(d[3])
        : "r"(a[0]), "r"(a[1]), "r"(a[2]), "r"(a[3]), "r"(b[0]), "r"(b[1]));
}

__global__ __launch_bounds__(256, 1) void k_pool_mma(
    const float* __restrict__ x, const float* __restrict__ S,
    float* __restrict__ T)
{
    extern __shared__ char smem[];
    const uint32_t sb = smem_u32(smem);
    const int tid = threadIdx.x;
    const int w   = tid >> 5;
    const int l   = tid & 31;
    const int c0  = blockIdx.x * CTILE;
    const int b   = blockIdx.y;
    const int ks  = blockIdx.z;                   // 0..2

    const int start = (ks == 0) ? 0 : (22 + 21 * (ks - 1));
    const int cnt   = (ks == 0) ? 22 : 21;

    const float* xb = x + ((size_t)b * C_ + c0) * HW_;
    const float* Sb = S + (size_t)b * M_ * HW_;

    const int cp = tid & 31;
    const int r0 = tid >> 5;

    const int arow = 16 * w + (l & 15);
    const int acol = (l >> 4) * 16;
    const int nrow = (l & 7) + ((l >> 4) << 3);
    const int bcol = ((l >> 3) & 1) * 16;

    float acc[8][4];
#pragma unroll
    for (int j = 0; j < 8; j++)
#pragma unroll
        for (int q = 0; q < 4; q++) acc[j][q] = 0.0f;

    float2 av[16], bv[8];
    {
        const int k0 = start * KC;
#pragma unroll
        for (int i = 0; i < 16; i++)
            av[i] = *(const float2*)(xb + (size_t)(r0 + 8 * i) * HW_ + k0 + 2 * cp);
#pragma unroll
        for (int i = 0; i < 8; i++)
            bv[i] = *(const float2*)(Sb + (size_t)(r0 + 8 * i) * HW_ + k0 + 2 * cp);
    }

    for (int ci = 0; ci < cnt; ci++) {
#pragma unroll
        for (int i = 0; i < 16; i++) {
            uint32_t sw = sw128((r0 + 8 * i) * 128 + 4 * cp);
            __nv_bfloat162 h = __floats2bfloat162_rn(av[i].x, av[i].y);
            float rx = av[i].x - __bfloat162float(h.x);
            float ry = av[i].y - __bfloat162float(h.y);
            __nv_bfloat162 lo = __floats2bfloat162_rn(rx, ry);
            *(uint32_t*)(smem + SM_AHI + sw) = *(uint32_t*)&h;
            *(uint32_t*)(smem + SM_ALO + sw) = *(uint32_t*)&lo;
        }
#pragma unroll
        for (int i = 0; i < 8; i++) {
            uint32_t sw = sw128((r0 + 8 * i) * 128 + 4 * cp);
            __nv_bfloat162 h = __floats2bfloat162_rn(bv[i].x, bv[i].y);
            float rx = bv[i].x - __bfloat162float(h.x);
            float ry = bv[i].y - __bfloat162float(h.y);
            __nv_bfloat162 lo = __floats2bfloat162_rn(rx, ry);
            *(uint32_t*)(smem + SM_BHI + sw) = *(uint32_t*)&h;
            *(uint32_t*)(smem + SM_BLO + sw) = *(uint32_t*)&lo;
        }
        __syncthreads();

        if (ci + 1 < cnt) {
            const int k1 = (start + ci + 1) * KC;
#pragma unroll
            for (int i = 0; i < 16; i++)
                av[i] = *(const float2*)(xb + (size_t)(r0 + 8 * i) * HW_ + k1 + 2 * cp);
#pragma unroll
            for (int i = 0; i < 8; i++)
                bv[i] = *(const float2*)(Sb + (size_t)(r0 + 8 * i) * HW_ + k1 + 2 * cp);
        }

#pragma unroll
        for (int s = 0; s < 4; s++) {
            uint32_t ah[4], al[4];
            uint32_t asw = sw128(arow * 128 + 32 * s + acol);
            ldsm4(ah, sb + SM_AHI + asw);
            ldsm4(al, sb + SM_ALO + asw);
#pragma unroll
            for (int jp = 0; jp < 4; jp++) {
                uint32_t bh[4], bl[4];
                uint32_t bsw = sw128((16 * jp + nrow) * 128 + 32 * s + bcol);
                ldsm4(bh, sb + SM_BHI + bsw);
                ldsm4(bl, sb + SM_BLO + bsw);
                mma_bf16(acc[2 * jp],     ah, bh);
                mma_bf16(acc[2 * jp],     ah, bl);
                mma_bf16(acc[2 * jp],     al, bh);
                mma_bf16(acc[2 * jp + 1], ah, bh + 2);
                mma_bf16(acc[2 * jp + 1], ah, bl + 2);
                mma_bf16(acc[2 * jp + 1], al, bh + 2);
            }
        }
        __syncthreads();
    }

    const int g  = l >> 2;
    const int q2 = (l & 3) * 2;
    float* tb = T + ((size_t)b * C_ + c0 + 16 * w) * M_;
#pragma unroll
    for (int j = 0; j < 8; j++) {
        atomicAdd(tb + (size_t)g * M_ + 8 * j + q2,           acc[j][0]);
        atomicAdd(tb + (size_t)g * M_ + 8 * j + q2 + 1,       acc[j][1]);
        atomicAdd(tb + (size_t)(g + 8) * M_ + 8 * j + q2,     acc[j][2]);
        atomicAdd(tb + (size_t)(g + 8) * M_ + 8 * j + q2 + 1, acc[j][3]);
    }
}

// ---------------- launch ----------------
extern "C" void kernel_launch(void* const* d_in, const int* in_sizes, int n_in,
                              void* d_out, int out_size)
{
    const float* x  = (const float*)d_in[0];
    const float* Vw = (const float*)d_in[1];
    const float* Vb = (const float*)d_in[2];
    const float* U  = (const float*)d_in[3];

    float* out = (float*)d_out;
    float* T = out;                           // [B, C, M]
    float* S = out + (size_t)B_ * C_ * M_;    // [B, M, N]

    cudaFuncSetAttribute(k_pool_mma, cudaFuncAttributeMaxDynamicSharedMemorySize,
                         SM_TOTAL);
    k_v<<<dim3(HW_ / 512, B_), 256>>>(x, Vw, Vb, T);
    k_softmax<<<dim3(HW_ / 128, B_), 128>>>(U, S);
    k_pool_mma<<<dim3(C_ / CTILE, B_, 3), 256, SM_TOTAL>>>(x, S, T);
}